// round 1
// baseline (speedup 1.0000x reference)
#include <cuda_runtime.h>
#include <math.h>

// Problem dims
constexpr int NB = 128;    // batch
constexpr int NL = 1024;   // seq len
constexpr int NE = 64;     // embed
constexpr int NH = 512;    // hidden
constexpr int NV = 96;     // vocab

// Recurrence kernel config
constexpr int G    = 64;   // CTAs (persistent)
constexpr int ROWS = 2;    // batch rows per CTA (G*ROWS == NB)
constexpr int NT   = 1024; // threads per CTA
constexpr int NKQ  = 8;    // k-split groups (NT / 128)
constexpr int KSEG = NH / NKQ; // 64 k-values per group
constexpr int KC   = 92;   // W_hh rows cached in SMEM

// SMEM budget for rnn kernel (floats): W-cache + h + partials
constexpr int SM_W = KC * NH;          // 47104
constexpr int SM_H = ROWS * NH;        // 1024
constexpr int SM_P = NKQ * ROWS * NH;  // 8192
constexpr int SMEM_RNN_BYTES = (SM_W + SM_H + SM_P) * 4; // 225280 B

// Logits kernel config
constexpr int LG_ROWS_PER_CTA = 64;
constexpr int SMEM_LOG_BYTES = NH * NV * 4; // 196608 B

// Scratch (device globals: allocation-free rule)
__device__ float g_proj[NV * NH];                      // 192 KB
__device__ float g_hs[(size_t)NB * NL * NH];           // 256 MB: all h_t

// ---------------------------------------------------------------------------
// Kernel 1: proj[v][h] = sum_e emb[v][e] * W_xh[e][h] + b_h[h]
// ---------------------------------------------------------------------------
__global__ void proj_kernel(const float* __restrict__ emb,
                            const float* __restrict__ Wxh,
                            const float* __restrict__ bh) {
    __shared__ float se[NE];
    int v = blockIdx.x;
    int h = threadIdx.x;            // 512 threads
    if (h < NE) se[h] = emb[v * NE + h];
    __syncthreads();
    float acc = bh[h];
    #pragma unroll
    for (int e = 0; e < NE; e++) {
        acc += se[e] * Wxh[e * NH + h];
    }
    g_proj[v * NH + h] = acc;
}

// ---------------------------------------------------------------------------
// Kernel 2: persistent recurrence. Each CTA owns ROWS batch rows; loops all
// 1024 timesteps. h lives in SMEM; W_hh rows [0,KC) cached in SMEM, the rest
// streamed from L2 every step. 8-way k-split partials reduced in SMEM.
// ---------------------------------------------------------------------------
__global__ __launch_bounds__(NT, 1)
void rnn_kernel(const void* __restrict__ xraw,
                const float* __restrict__ h0,
                const float* __restrict__ Whh,
                float* __restrict__ finalh) {
    extern __shared__ float sm[];
    float* smW = sm;                 // [KC][NH]
    float* smH = sm + SM_W;          // [ROWS][NH]
    float* smP = smH + SM_H;         // [NKQ][ROWS][NH]
    __shared__ int smTok[ROWS];

    const int tid = threadIdx.x;
    const int r0  = blockIdx.x * ROWS;

    // Detect x dtype: int64 (odd int32 words all zero, values < NV) vs int32.
    const int* xi = (const int*)xraw;
    bool is64 = true;
    for (int i = 1; i < 128; i += 2) {
        if (xi[i] != 0) { is64 = false; break; }
    }
    const long long* x64 = (const long long*)xraw;
    const int*       x32 = (const int*)xraw;

    // Load W_hh cache (rows [0,KC)) via float4
    {
        const float4* Wv = (const float4*)Whh;
        float4* smWv = (float4*)smW;
        for (int i = tid; i < SM_W / 4; i += NT) smWv[i] = Wv[i];
    }
    // Init h from input `hidden`
    for (int i = tid; i < ROWS * NH; i += NT) smH[i] = h0[(size_t)r0 * NH + i];
    __syncthreads();

    const int kq = tid >> 7;              // 0..7
    const int cc = (tid & 127) * 4;       // column base (float4)
    const int rr = tid >> 9;              // 0..1 (reduce phase row)
    const int jj = tid & (NH - 1);        // 0..511 (reduce phase col)

    const int kbeg = kq * KSEG;
    const int kend = kbeg + KSEG;
    const int ksmEnd = (kend < KC) ? kend : KC;
    const int kglBeg = (kbeg > KC) ? kbeg : KC;

    for (int t = 0; t < NL; t++) {
        if (tid < ROWS) {
            size_t idx = (size_t)(r0 + tid) * NL + t;
            smTok[tid] = is64 ? (int)x64[idx] : x32[idx];
        }

        float a00 = 0.f, a01 = 0.f, a02 = 0.f, a03 = 0.f;
        float a10 = 0.f, a11 = 0.f, a12 = 0.f, a13 = 0.f;

        // SMEM-cached W rows
        #pragma unroll 4
        for (int k = kbeg; k < ksmEnd; k++) {
            float4 w = *(const float4*)&smW[k * NH + cc];
            float f0 = smH[k];
            float f1 = smH[NH + k];
            a00 += f0 * w.x; a01 += f0 * w.y; a02 += f0 * w.z; a03 += f0 * w.w;
            a10 += f1 * w.x; a11 += f1 * w.y; a12 += f1 * w.z; a13 += f1 * w.w;
        }
        // Streamed W rows (L2)
        #pragma unroll 4
        for (int k = kglBeg; k < kend; k++) {
            float4 w = *(const float4*)&Whh[(size_t)k * NH + cc];
            float f0 = smH[k];
            float f1 = smH[NH + k];
            a00 += f0 * w.x; a01 += f0 * w.y; a02 += f0 * w.z; a03 += f0 * w.w;
            a10 += f1 * w.x; a11 += f1 * w.y; a12 += f1 * w.z; a13 += f1 * w.w;
        }

        *(float4*)&smP[(kq * ROWS + 0) * NH + cc] = make_float4(a00, a01, a02, a03);
        *(float4*)&smP[(kq * ROWS + 1) * NH + cc] = make_float4(a10, a11, a12, a13);
        __syncthreads();

        // Reduce partials + xh + tanh; write back h, store to g_hs
        {
            float s = 0.f;
            #pragma unroll
            for (int q = 0; q < NKQ; q++) s += smP[(q * ROWS + rr) * NH + jj];
            s += g_proj[smTok[rr] * NH + jj];
            float hn = tanhf(s);
            g_hs[((size_t)(r0 + rr) * NL + t) * NH + jj] = hn;
            smH[rr * NH + jj] = hn;
            if (t == NL - 1 && finalh) finalh[(r0 + rr) * NH + jj] = hn;
        }
        __syncthreads();
    }
}

// ---------------------------------------------------------------------------
// Kernel 3: logits[row][c] = sum_k hs[row][k] * fc_w[k][c] + fc_b[c]
// fc_w in SMEM (192 KB). Each warp owns 4 rows (warp-uniform hs loads →
// single L2 request), each lane owns 3 columns → 4x3 register tile.
// ---------------------------------------------------------------------------
__global__ __launch_bounds__(512, 1)
void logits_kernel(const float* __restrict__ fcw,
                   const float* __restrict__ fcb,
                   float* __restrict__ out) {
    extern __shared__ float smFc[];  // [NH][NV]
    const int tid = threadIdx.x;
    {
        const float4* fv = (const float4*)fcw;
        float4* sv = (float4*)smFc;
        for (int i = tid; i < NH * NV / 4; i += 512) sv[i] = fv[i];
    }
    __syncthreads();

    const int lane = tid & 31;
    const int warp = tid >> 5;
    const int c = lane * 3;                                  // 32*3 = 96 cols
    const size_t row0 = (size_t)blockIdx.x * LG_ROWS_PER_CTA + warp * 4;
    const float* hsr = g_hs + row0 * NH;

    float acc[4][3];
    #pragma unroll
    for (int i = 0; i < 4; i++)
        #pragma unroll
        for (int j = 0; j < 3; j++) acc[i][j] = 0.f;

    #pragma unroll 2
    for (int k4 = 0; k4 < NH / 4; k4++) {
        float hv[4][4];
        #pragma unroll
        for (int i = 0; i < 4; i++) {
            float4 v = *(const float4*)&hsr[(size_t)i * NH + 4 * k4];
            hv[i][0] = v.x; hv[i][1] = v.y; hv[i][2] = v.z; hv[i][3] = v.w;
        }
        #pragma unroll
        for (int kk = 0; kk < 4; kk++) {
            int k = 4 * k4 + kk;
            float w0 = smFc[k * NV + c + 0];
            float w1 = smFc[k * NV + c + 1];
            float w2 = smFc[k * NV + c + 2];
            #pragma unroll
            for (int i = 0; i < 4; i++) {
                acc[i][0] += hv[i][kk] * w0;
                acc[i][1] += hv[i][kk] * w1;
                acc[i][2] += hv[i][kk] * w2;
            }
        }
    }

    float b0 = fcb[c + 0], b1 = fcb[c + 1], b2 = fcb[c + 2];
    #pragma unroll
    for (int i = 0; i < 4; i++) {
        size_t o = (row0 + i) * NV + c;
        out[o + 0] = acc[i][0] + b0;
        out[o + 1] = acc[i][1] + b1;
        out[o + 2] = acc[i][2] + b2;
    }
}

// ---------------------------------------------------------------------------
// Launch
// ---------------------------------------------------------------------------
extern "C" void kernel_launch(void* const* d_in, const int* in_sizes, int n_in,
                              void* d_out, int out_size) {
    const void*  x      = d_in[0];                 // [B,L] int64 or int32
    const float* hidden = (const float*)d_in[1];   // [B,H]
    const float* emb    = (const float*)d_in[2];   // [V,E]
    const float* Wxh    = (const float*)d_in[3];   // [E,H]
    const float* Whh    = (const float*)d_in[4];   // [H,H]
    const float* bh     = (const float*)d_in[5];   // [H]
    const float* fcw    = (const float*)d_in[6];   // [H,V]
    const float* fcb    = (const float*)d_in[7];   // [V]

    float* out = (float*)d_out;                    // logits [B,L,V] ...
    const size_t logitsN = (size_t)NB * NL * NV;
    float* finalh = (out_size >= (int)(logitsN + (size_t)NB * NH))
                        ? out + logitsN : nullptr; // ... then final_h [B,H]

    cudaFuncSetAttribute(rnn_kernel,
                         cudaFuncAttributeMaxDynamicSharedMemorySize,
                         SMEM_RNN_BYTES);
    cudaFuncSetAttribute(logits_kernel,
                         cudaFuncAttributeMaxDynamicSharedMemorySize,
                         SMEM_LOG_BYTES);

    proj_kernel<<<NV, NH>>>(emb, Wxh, bh);
    rnn_kernel<<<G, NT, SMEM_RNN_BYTES>>>(x, hidden, Whh, finalh);
    logits_kernel<<<(NB * NL) / LG_ROWS_PER_CTA, 512, SMEM_LOG_BYTES>>>(fcw, fcb, out);
}

// round 2
// speedup vs baseline: 1.2890x; 1.2890x over previous
#include <cuda_runtime.h>
#include <math.h>
#include <stdint.h>

// Problem dims
constexpr int NB = 128;    // batch
constexpr int NL = 1024;   // seq len
constexpr int NE = 64;     // embed
constexpr int NH = 512;    // hidden
constexpr int NV = 96;     // vocab

// RNN cluster kernel config
constexpr int CS   = 8;          // CTAs per cluster (cluster size)
constexpr int RPC  = 8;          // batch rows per cluster
constexpr int NCL  = NB / RPC;   // 16 clusters
constexpr int GRNN = NCL * CS;   // 128 CTAs
constexpr int TRNN = 512;        // threads per CTA (one per output col)
constexpr int KS   = NH / CS;    // 64 k-values owned per CTA

// Dynamic SMEM layout (floats):
//   buf [2][CS][RPC][KS]  partial-sum mailboxes (double-buffered)
//   proj[NV][KS]          token-projection slice for this CTA's columns
//   h   [RPC][KS]         local hidden slice
//   tok [2][RPC]          (ints) double-buffered tokens
constexpr int SM_BUF  = 2 * CS * RPC * KS;  // 8192 floats
constexpr int SM_PROJ = NV * KS;            // 6144 floats
constexpr int SM_HH   = RPC * KS;           // 512 floats
constexpr int RNN_SMEM_BYTES = (SM_BUF + SM_PROJ + SM_HH) * 4 + 2 * RPC * 4 + 16;

// Logits kernel config
constexpr int LG_ROWS_PER_CTA = 64;
constexpr int SMEM_LOG_BYTES = NH * NV * 4; // 196608 B

// Scratch (device globals: allocation-free rule)
__device__ float g_proj[NV * NH];                 // 192 KB
__device__ float g_hs[(size_t)NB * NL * NH];      // 256 MB: all h_t

// ---------------------------------------------------------------------------
// Helpers
// ---------------------------------------------------------------------------
__device__ __forceinline__ uint32_t smem_u32(const void* p) {
    return (uint32_t)__cvta_generic_to_shared(p);
}

__device__ __forceinline__ unsigned long long packf2(float lo, float hi) {
    return (unsigned long long)__float_as_uint(lo) |
           ((unsigned long long)__float_as_uint(hi) << 32);
}

// Packed fp32x2 FMA: acc.lo += a.lo*b.lo, acc.hi += a.hi*b.hi (exact fp32)
#define FMA2(acc, a, b) \
    asm volatile("fma.rn.f32x2 %0, %1, %2, %0;" : "+l"(acc) : "l"(a), "l"(b))

#define CLUSTER_SYNC_() do { \
    asm volatile("barrier.cluster.arrive.aligned;" ::: "memory"); \
    asm volatile("barrier.cluster.wait.aligned;"   ::: "memory"); \
} while (0)

// ---------------------------------------------------------------------------
// Kernel 1: proj[v][h] = sum_e emb[v][e] * W_xh[e][h] + b_h[h]
// ---------------------------------------------------------------------------
__global__ void proj_kernel(const float* __restrict__ emb,
                            const float* __restrict__ Wxh,
                            const float* __restrict__ bh) {
    __shared__ float se[NE];
    int v = blockIdx.x;
    int h = threadIdx.x;            // 512 threads
    if (h < NE) se[h] = emb[v * NE + h];
    __syncthreads();
    float acc = bh[h];
    #pragma unroll
    for (int e = 0; e < NE; e++) acc += se[e] * Wxh[e * NH + h];
    g_proj[v * NH + h] = acc;
}

// ---------------------------------------------------------------------------
// Kernel 2: clustered recurrence. 16 clusters x 8 CTAs. Cluster owns 8 batch
// rows; CTA c owns k/col slice [64c,64c+64). W_hh slice lives in REGISTERS
// (64 floats/thread), h slice in SMEM. Each step: compute partials for all
// 512 cols over local 64-k slice (fma.rn.f32x2), scatter col-slices to owner
// CTAs via st.shared::cluster, cluster.sync, reduce + proj + tanh locally.
// Owner's output cols == its next-step k-slice, so no h broadcast needed.
// ---------------------------------------------------------------------------
__global__ __launch_bounds__(TRNN, 1)
void rnn2_kernel(const void* __restrict__ xraw,
                 const float* __restrict__ h0,
                 const float* __restrict__ Whh,
                 float* __restrict__ finalh) {
    extern __shared__ float sm[];
    float* buf   = sm;                       // [2][CS][RPC][KS]
    float* sproj = sm + SM_BUF;              // [NV][KS]
    float* sh    = sproj + SM_PROJ;          // [RPC][KS]
    int*   stok  = (int*)(sh + SM_HH);       // [2][RPC]

    const int tid     = threadIdx.x;
    const int rank    = blockIdx.x & (CS - 1);
    const int cl      = blockIdx.x >> 3;
    const int row0    = cl * RPC;
    const int colbase = rank * KS;
    const int j       = tid;            // global output column 0..511
    const int owner   = j >> 6;         // owning CTA rank of column j
    const int jl      = j & (KS - 1);
    const int rr      = tid >> 6;       // reduce-phase row
    const int rjl     = tid & (KS - 1); // reduce-phase col-in-slice

    // Detect x dtype: int64 (odd int32 words all zero) vs int32.
    const int* xi = (const int*)xraw;
    bool is64 = true;
    for (int i = 1; i < 128; i += 2) {
        if (xi[i] != 0) { is64 = false; break; }
    }
    const long long* x64 = (const long long*)xraw;
    const int*       x32 = (const int*)xraw;

    // W_hh slice -> registers, packed as (W[kb+2p][j], W[kb+2p+1][j])
    unsigned long long wreg[KS / 2];
    {
        const float* Wb = Whh + (size_t)colbase * NH + j;
        #pragma unroll
        for (int p = 0; p < KS / 2; p++) {
            float lo = Wb[(size_t)(2 * p) * NH];
            float hi = Wb[(size_t)(2 * p + 1) * NH];
            wreg[p] = packf2(lo, hi);
        }
    }
    // proj slice for this CTA's columns
    for (int i = tid; i < SM_PROJ; i += TRNN) {
        int v = i >> 6; int c = i & (KS - 1);
        sproj[i] = g_proj[v * NH + colbase + c];
    }
    // h init (thread -> (rr, rjl))
    sh[tid] = h0[(size_t)(row0 + rr) * NH + colbase + rjl];
    // token prime for t=0 (slot 0)
    if (tid < RPC) {
        size_t idx = (size_t)(row0 + tid) * NL;
        stok[tid] = is64 ? (int)x64[idx] : x32[idx];
    }
    __syncthreads();
    CLUSTER_SYNC_();   // whole cluster initialized before first scatter

    // Remote base address of owner CTA's buf (offsets are position-invariant)
    uint32_t rbase;
    {
        uint32_t lbase = smem_u32(buf);
        asm volatile("mapa.shared::cluster.u32 %0, %1, %2;"
                     : "=r"(rbase) : "r"(lbase), "r"(owner));
    }

    for (int t = 0; t < NL; t++) {
        const int pb = t & 1;

        // Prefetch next step's tokens (latency hidden under compute)
        int tok_next = 0;
        if (tid < RPC && t + 1 < NL) {
            size_t idx = (size_t)(row0 + tid) * NL + (t + 1);
            tok_next = is64 ? (int)x64[idx] : x32[idx];
        }

        // ---- compute: partial[r][j] over local k-slice, packed f32x2 ----
        unsigned long long acc[RPC];
        #pragma unroll
        for (int r = 0; r < RPC; r++) acc[r] = 0ull;  // (0.f,0.f)

        #pragma unroll
        for (int p2 = 0; p2 < KS / 4; p2++) {
            unsigned long long w0 = wreg[2 * p2];
            unsigned long long w1 = wreg[2 * p2 + 1];
            #pragma unroll
            for (int r = 0; r < RPC; r++) {
                ulonglong2 hh = *(const ulonglong2*)&sh[r * KS + p2 * 4];
                FMA2(acc[r], w0, hh.x);
                FMA2(acc[r], w1, hh.y);
            }
        }

        // ---- scatter partials to owner CTA's mailbox ----
        #pragma unroll
        for (int r = 0; r < RPC; r++) {
            float lo = __uint_as_float((uint32_t)acc[r]);
            float hi = __uint_as_float((uint32_t)(acc[r] >> 32));
            float v  = lo + hi;
            uint32_t ra = rbase +
                (uint32_t)((((pb * CS + rank) * RPC + r) * KS + jl) * 4);
            asm volatile("st.shared::cluster.f32 [%0], %1;"
                         :: "r"(ra), "f"(v) : "memory");
        }

        CLUSTER_SYNC_();   // all scatters visible cluster-wide

        // ---- reduce own columns: sum 8 partials + proj + tanh ----
        {
            float s = 0.f;
            #pragma unroll
            for (int s8 = 0; s8 < CS; s8++)
                s += buf[((pb * CS + s8) * RPC + rr) * KS + rjl];
            s += sproj[stok[pb * RPC + rr] * KS + rjl];
            float hn = tanhf(s);
            sh[rr * KS + rjl] = hn;
            g_hs[((size_t)(row0 + rr) * NL + t) * NH + colbase + rjl] = hn;
            if (t == NL - 1 && finalh)
                finalh[(row0 + rr) * NH + colbase + rjl] = hn;
        }
        if (tid < RPC) stok[((t + 1) & 1) * RPC + tid] = tok_next;
        __syncthreads();   // h + tok ready for next step
    }
}

// ---------------------------------------------------------------------------
// Kernel 3: logits[row][c] = sum_k hs[row][k] * fc_w[k][c] + fc_b[c]
// ---------------------------------------------------------------------------
__global__ __launch_bounds__(512, 1)
void logits_kernel(const float* __restrict__ fcw,
                   const float* __restrict__ fcb,
                   float* __restrict__ out) {
    extern __shared__ float smFc[];  // [NH][NV]
    const int tid = threadIdx.x;
    {
        const float4* fv = (const float4*)fcw;
        float4* sv = (float4*)smFc;
        for (int i = tid; i < NH * NV / 4; i += 512) sv[i] = fv[i];
    }
    __syncthreads();

    const int lane = tid & 31;
    const int warp = tid >> 5;
    const int c = lane * 3;                                  // 32*3 = 96 cols
    const size_t row0 = (size_t)blockIdx.x * LG_ROWS_PER_CTA + warp * 4;
    const float* hsr = g_hs + row0 * NH;

    float acc[4][3];
    #pragma unroll
    for (int i = 0; i < 4; i++)
        #pragma unroll
        for (int jx = 0; jx < 3; jx++) acc[i][jx] = 0.f;

    #pragma unroll 2
    for (int k4 = 0; k4 < NH / 4; k4++) {
        float hv[4][4];
        #pragma unroll
        for (int i = 0; i < 4; i++) {
            float4 v = *(const float4*)&hsr[(size_t)i * NH + 4 * k4];
            hv[i][0] = v.x; hv[i][1] = v.y; hv[i][2] = v.z; hv[i][3] = v.w;
        }
        #pragma unroll
        for (int kk = 0; kk < 4; kk++) {
            int k = 4 * k4 + kk;
            float w0 = smFc[k * NV + c + 0];
            float w1 = smFc[k * NV + c + 1];
            float w2 = smFc[k * NV + c + 2];
            #pragma unroll
            for (int i = 0; i < 4; i++) {
                acc[i][0] += hv[i][kk] * w0;
                acc[i][1] += hv[i][kk] * w1;
                acc[i][2] += hv[i][kk] * w2;
            }
        }
    }

    float b0 = fcb[c + 0], b1 = fcb[c + 1], b2 = fcb[c + 2];
    #pragma unroll
    for (int i = 0; i < 4; i++) {
        size_t o = (row0 + i) * NV + c;
        out[o + 0] = acc[i][0] + b0;
        out[o + 1] = acc[i][1] + b1;
        out[o + 2] = acc[i][2] + b2;
    }
}

// ---------------------------------------------------------------------------
// Launch
// ---------------------------------------------------------------------------
extern "C" void kernel_launch(void* const* d_in, const int* in_sizes, int n_in,
                              void* d_out, int out_size) {
    const void*  x      = d_in[0];                 // [B,L] int64 or int32
    const float* hidden = (const float*)d_in[1];   // [B,H]
    const float* emb    = (const float*)d_in[2];   // [V,E]
    const float* Wxh    = (const float*)d_in[3];   // [E,H]
    const float* Whh    = (const float*)d_in[4];   // [H,H]
    const float* bh     = (const float*)d_in[5];   // [H]
    const float* fcw    = (const float*)d_in[6];   // [H,V]
    const float* fcb    = (const float*)d_in[7];   // [V]

    float* out = (float*)d_out;                    // logits [B,L,V] ...
    const size_t logitsN = (size_t)NB * NL * NV;
    float* finalh = (out_size >= (int)(logitsN + (size_t)NB * NH))
                        ? out + logitsN : nullptr; // ... then final_h [B,H]

    cudaFuncSetAttribute(rnn2_kernel,
                         cudaFuncAttributeMaxDynamicSharedMemorySize,
                         RNN_SMEM_BYTES);
    cudaFuncSetAttribute(logits_kernel,
                         cudaFuncAttributeMaxDynamicSharedMemorySize,
                         SMEM_LOG_BYTES);

    proj_kernel<<<NV, NH>>>(emb, Wxh, bh);

    // Clustered recurrence launch (8-CTA clusters)
    {
        cudaLaunchConfig_t cfg = {};
        cfg.gridDim  = dim3(GRNN, 1, 1);
        cfg.blockDim = dim3(TRNN, 1, 1);
        cfg.dynamicSmemBytes = RNN_SMEM_BYTES;
        cfg.stream = 0;
        cudaLaunchAttribute attr[1];
        attr[0].id = cudaLaunchAttributeClusterDimension;
        attr[0].val.clusterDim.x = CS;
        attr[0].val.clusterDim.y = 1;
        attr[0].val.clusterDim.z = 1;
        cfg.attrs = attr;
        cfg.numAttrs = 1;
        cudaLaunchKernelEx(&cfg, rnn2_kernel, x, hidden, Whh, finalh);
    }

    logits_kernel<<<(NB * NL) / LG_ROWS_PER_CTA, 512, SMEM_LOG_BYTES>>>(fcw, fcb, out);
}

// round 6
// speedup vs baseline: 1.3844x; 1.0740x over previous
#include <cuda_runtime.h>
#include <math.h>
#include <stdint.h>

// Problem dims
constexpr int NB = 128;    // batch
constexpr int NL = 1024;   // seq len
constexpr int NE = 64;     // embed
constexpr int NH = 512;    // hidden
constexpr int NV = 96;     // vocab

// RNN cluster kernel config
constexpr int CS   = 8;          // CTAs per cluster
constexpr int RPC  = 8;          // batch rows per cluster
constexpr int NCL  = NB / RPC;   // 16 clusters
constexpr int GRNN = NCL * CS;   // 128 CTAs
constexpr int TRNN = 512;        // threads per CTA (one per output col)
constexpr int KS   = NH / CS;    // 64 k-values owned per CTA

// Dynamic SMEM (floats):
//   buf [2][CS][RPC][KS]  partial-sum mailboxes (double-buffered)   8192
//   proj[NV][KS]          token projection slice for this CTA       6144
//   h   [RPC][KS]         local hidden slice                         512
//   tok [2][RPC]          ints
constexpr int SM_BUF  = 2 * CS * RPC * KS;
constexpr int SM_PROJ = NV * KS;
constexpr int SM_HH   = RPC * KS;
constexpr int RNN_SMEM_BYTES = (SM_BUF + SM_PROJ + SM_HH) * 4 + 2 * RPC * 4 + 16;

// Logits kernel config (persistent)
constexpr int LG_GRID = 148;
constexpr int LG_TILE = 64;                    // rows per tile
constexpr int LG_NTILES = NB * NL / LG_TILE;   // 2048
constexpr int SMEM_LOG_BYTES = (NH / 2) * NV * 8; // 196608 B (float2 pairs)

// Scratch (device global: allocation-free rule)
__device__ float g_hs[(size_t)NB * NL * NH];   // 256 MB: all h_t

// ---------------------------------------------------------------------------
// Helpers
// ---------------------------------------------------------------------------
__device__ __forceinline__ uint32_t smem_u32(const void* p) {
    return (uint32_t)__cvta_generic_to_shared(p);
}
__device__ __forceinline__ unsigned long long packf2(float lo, float hi) {
    return (unsigned long long)__float_as_uint(lo) |
           ((unsigned long long)__float_as_uint(hi) << 32);
}
__device__ __forceinline__ float f2lo(unsigned long long v) {
    return __uint_as_float((uint32_t)v);
}
__device__ __forceinline__ float f2hi(unsigned long long v) {
    return __uint_as_float((uint32_t)(v >> 32));
}
// Packed fp32x2 FMA (exact fp32 per lane)
#define FMA2(acc, a, b) \
    asm volatile("fma.rn.f32x2 %0, %1, %2, %0;" : "+l"(acc) : "l"(a), "l"(b))

#define CL_ARRIVE() asm volatile("barrier.cluster.arrive.aligned;" ::: "memory")
#define CL_WAIT()   asm volatile("barrier.cluster.wait.aligned;"   ::: "memory")

// ---------------------------------------------------------------------------
// Kernel 1: clustered recurrence with fused input projection.
// 16 clusters x 8 CTAs. Cluster owns 8 batch rows; CTA c owns k/col slice
// [64c,64c+64). W_hh slice in REGISTERS (64 floats/thread, r-outer loop keeps
// live set ~95 regs -> no spills). Per step: per-row partials (fma.rn.f32x2)
// scattered to owner CTA right after each row completes; split cluster
// barrier hides the deferred g_hs store + token prefetch.
// ---------------------------------------------------------------------------
__global__ __launch_bounds__(TRNN, 1)
void rnn3_kernel(const void* __restrict__ xraw,
                 const float* __restrict__ h0,
                 const float* __restrict__ Whh,
                 const float* __restrict__ emb,
                 const float* __restrict__ Wxh,
                 const float* __restrict__ bh,
                 float* __restrict__ finalh) {
    extern __shared__ float sm[];
    float* buf   = sm;                       // [2][CS][RPC][KS]
    float* sproj = sm + SM_BUF;              // [NV][KS]
    float* sh    = sproj + SM_PROJ;          // [RPC][KS]
    int*   stok  = (int*)(sh + SM_HH);       // [2][RPC]

    const int tid     = threadIdx.x;
    const int rank    = blockIdx.x & (CS - 1);
    const int cl      = blockIdx.x >> 3;
    const int row0    = cl * RPC;
    const int colbase = rank * KS;
    const int j       = tid;            // global output column 0..511
    const int owner   = j >> 6;         // owning CTA rank of column j
    const int jl      = j & (KS - 1);
    const int rr      = tid >> 6;       // reduce-phase row
    const int rjl     = tid & (KS - 1); // reduce-phase col-in-slice

    // Detect x dtype: int64 (odd int32 words all zero) vs int32.
    const int* xi = (const int*)xraw;
    bool is64 = true;
    for (int i = 1; i < 128; i += 2) {
        if (xi[i] != 0) { is64 = false; break; }
    }
    const long long* x64 = (const long long*)xraw;
    const int*       x32 = (const int*)xraw;

    // ---- fused proj: sproj[v][c] = bh[cb+c] + sum_e emb[v][e]*Wxh[e][cb+c]
    // Stage emb (6144 f) and Wxh col-slice (4096 f) in smem scratch
    // (overlaps buf+sproj regions; results go through registers first).
    {
        float* semb = sm;            // [NV][NE]     6144 floats
        float* swx  = sm + NV * NE;  // [NE][KS]     4096 floats
        for (int i = tid; i < NV * NE; i += TRNN) semb[i] = emb[i];
        for (int i = tid; i < NE * KS; i += TRNN) {
            int e = i >> 6, c = i & (KS - 1);
            swx[i] = Wxh[e * NH + colbase + c];
        }
        __syncthreads();
        float pr[NV * KS / TRNN];   // 12 outputs per thread
        #pragma unroll
        for (int o = 0; o < NV * KS / TRNN; o++) {
            int idx = o * TRNN + tid;
            int v = idx >> 6, c = idx & (KS - 1);
            float acc = bh[colbase + c];
            #pragma unroll 8
            for (int e = 0; e < NE; e++) acc += semb[v * NE + e] * swx[e * KS + c];
            pr[o] = acc;
        }
        __syncthreads();
        #pragma unroll
        for (int o = 0; o < NV * KS / TRNN; o++) sproj[o * TRNN + tid] = pr[o];
    }

    // W_hh slice -> registers, packed (W[cb+2p][j], W[cb+2p+1][j])
    unsigned long long wreg[KS / 2];
    {
        const float* Wb = Whh + (size_t)colbase * NH + j;
        #pragma unroll
        for (int p = 0; p < KS / 2; p++) {
            wreg[p] = packf2(Wb[(size_t)(2 * p) * NH], Wb[(size_t)(2 * p + 1) * NH]);
        }
    }
    // h init; tokens t=0
    sh[tid] = h0[(size_t)(row0 + rr) * NH + colbase + rjl];
    if (tid < RPC) {
        size_t idx = (size_t)(row0 + tid) * NL;
        stok[tid] = is64 ? (int)x64[idx] : x32[idx];
    }
    __syncthreads();
    CL_ARRIVE(); CL_WAIT();   // cluster initialized

    // Remote base address of owner CTA's mailbox
    uint32_t rbase;
    {
        uint32_t lbase = smem_u32(buf);
        asm volatile("mapa.shared::cluster.u32 %0, %1, %2;"
                     : "=r"(rbase) : "r"(lbase), "r"(owner));
    }

    float* gdst = g_hs + (size_t)(row0 + rr) * NL * NH + colbase + rjl;
    float hprev = 0.f;

    for (int t = 0; t < NL; t++) {
        const int pb = t & 1;

        // ---- compute + immediate scatter, one batch row at a time ----
        #pragma unroll 2
        for (int r = 0; r < RPC; r++) {
            unsigned long long a0 = 0ull, a1 = 0ull;
            #pragma unroll
            for (int p2 = 0; p2 < KS / 4; p2++) {
                ulonglong2 hh = *(const ulonglong2*)&sh[r * KS + p2 * 4];
                FMA2(a0, wreg[2 * p2],     hh.x);
                FMA2(a1, wreg[2 * p2 + 1], hh.y);
            }
            float v = (f2lo(a0) + f2hi(a0)) + (f2lo(a1) + f2hi(a1));
            uint32_t ra = rbase +
                (uint32_t)((((pb * CS + rank) * RPC + r) * KS + jl) * 4);
            asm volatile("st.shared::cluster.f32 [%0], %1;"
                         :: "r"(ra), "f"(v) : "memory");
        }

        CL_ARRIVE();

        // deferred work under the barrier: previous h -> gmem, next token
        if (t > 0) gdst[(size_t)(t - 1) * NH] = hprev;
        int tok_next = 0;
        if (tid < RPC && t + 1 < NL) {
            size_t idx = (size_t)(row0 + tid) * NL + (t + 1);
            tok_next = is64 ? (int)x64[idx] : x32[idx];
        }

        CL_WAIT();

        // ---- reduce own column: 8 partials + proj + tanh ----
        {
            float s = 0.f;
            #pragma unroll
            for (int s8 = 0; s8 < CS; s8++)
                s += buf[((pb * CS + s8) * RPC + rr) * KS + rjl];
            s += sproj[stok[pb * RPC + rr] * KS + rjl];
            hprev = tanhf(s);
            sh[rr * KS + rjl] = hprev;
        }
        if (tid < RPC) stok[((t + 1) & 1) * RPC + tid] = tok_next;
        __syncthreads();
    }

    gdst[(size_t)(NL - 1) * NH] = hprev;
    if (finalh) finalh[(row0 + rr) * NH + colbase + rjl] = hprev;
}

// ---------------------------------------------------------------------------
// Kernel 2: persistent logits GEMM, fp32x2 packed FMA.
// fc_w loaded ONCE per CTA into SMEM as k-pairs: spk[k2][c] = (w[2k2][c],
// w[2k2+1][c]). Warp owns 4 rows; lane owns cols {lane, lane+32, lane+64}.
// ---------------------------------------------------------------------------
__global__ __launch_bounds__(512, 1)
void logits2_kernel(const float* __restrict__ fcw,
                    const float* __restrict__ fcb,
                    float* __restrict__ out) {
    extern __shared__ float2 spk[];  // [NH/2][NV]
    const int tid  = threadIdx.x;
    const int lane = tid & 31;
    const int warp = tid >> 5;

    for (int i = tid; i < (NH / 2) * NV; i += 512) {
        int k2 = i / NV, c = i - k2 * NV;
        spk[i] = make_float2(fcw[(2 * k2) * NV + c], fcw[(2 * k2 + 1) * NV + c]);
    }
    float b[3];
    #pragma unroll
    for (int g = 0; g < 3; g++) b[g] = fcb[g * 32 + lane];
    __syncthreads();

    for (int tile = blockIdx.x; tile < LG_NTILES; tile += gridDim.x) {
        const size_t row0 = (size_t)tile * LG_TILE + warp * 4;
        const float* hsr = g_hs + row0 * NH;

        unsigned long long acc[4][3];
        #pragma unroll
        for (int i = 0; i < 4; i++)
            #pragma unroll
            for (int g = 0; g < 3; g++) acc[i][g] = 0ull;

        for (int k4 = 0; k4 < NH / 4; k4++) {
            unsigned long long hp[4][2];
            #pragma unroll
            for (int i = 0; i < 4; i++) {
                float4 v = *(const float4*)&hsr[(size_t)i * NH + 4 * k4];
                hp[i][0] = packf2(v.x, v.y);
                hp[i][1] = packf2(v.z, v.w);
            }
            #pragma unroll
            for (int kk = 0; kk < 2; kk++) {
                int k2 = 2 * k4 + kk;
                #pragma unroll
                for (int g = 0; g < 3; g++) {
                    float2 w = spk[k2 * NV + g * 32 + lane];
                    unsigned long long wp = packf2(w.x, w.y);
                    #pragma unroll
                    for (int i = 0; i < 4; i++) FMA2(acc[i][g], hp[i][kk], wp);
                }
            }
        }
        #pragma unroll
        for (int i = 0; i < 4; i++)
            #pragma unroll
            for (int g = 0; g < 3; g++) {
                float s = f2lo(acc[i][g]) + f2hi(acc[i][g]) + b[g];
                out[(row0 + i) * NV + g * 32 + lane] = s;
            }
    }
}

// ---------------------------------------------------------------------------
// Launch
// ---------------------------------------------------------------------------
extern "C" void kernel_launch(void* const* d_in, const int* in_sizes, int n_in,
                              void* d_out, int out_size) {
    const void*  x      = d_in[0];                 // [B,L] int64 or int32
    const float* hidden = (const float*)d_in[1];   // [B,H]
    const float* emb    = (const float*)d_in[2];   // [V,E]
    const float* Wxh    = (const float*)d_in[3];   // [E,H]
    const float* Whh    = (const float*)d_in[4];   // [H,H]
    const float* bh     = (const float*)d_in[5];   // [H]
    const float* fcw    = (const float*)d_in[6];   // [H,V]
    const float* fcb    = (const float*)d_in[7];   // [V]

    float* out = (float*)d_out;                    // logits [B,L,V] ...
    const size_t logitsN = (size_t)NB * NL * NV;
    float* finalh = (out_size >= (int)(logitsN + (size_t)NB * NH))
                        ? out + logitsN : nullptr; // ... then final_h [B,H]

    cudaFuncSetAttribute(rnn3_kernel,
                         cudaFuncAttributeMaxDynamicSharedMemorySize,
                         RNN_SMEM_BYTES);
    cudaFuncSetAttribute(logits2_kernel,
                         cudaFuncAttributeMaxDynamicSharedMemorySize,
                         SMEM_LOG_BYTES);

    // Clustered recurrence (8-CTA clusters), proj fused into prologue
    {
        cudaLaunchConfig_t cfg = {};
        cfg.gridDim  = dim3(GRNN, 1, 1);
        cfg.blockDim = dim3(TRNN, 1, 1);
        cfg.dynamicSmemBytes = RNN_SMEM_BYTES;
        cfg.stream = 0;
        cudaLaunchAttribute attr[1];
        attr[0].id = cudaLaunchAttributeClusterDimension;
        attr[0].val.clusterDim.x = CS;
        attr[0].val.clusterDim.y = 1;
        attr[0].val.clusterDim.z = 1;
        cfg.attrs = attr;
        cfg.numAttrs = 1;
        cudaLaunchKernelEx(&cfg, rnn3_kernel, x, hidden, Whh, emb, Wxh, bh, finalh);
    }

    logits2_kernel<<<LG_GRID, 512, SMEM_LOG_BYTES>>>(fcw, fcb, out);
}